// round 9
// baseline (speedup 1.0000x reference)
#include <cuda_runtime.h>
#include <cstdint>

// Problem constants
#define BSZ   16
#define NDIM  256
#define DDIM  64
#define MCOLS (NDIM * DDIM)      // 16384
#define ABATCH (NDIM * NDIM)     // 65536
#define BBATCH (NDIM * MCOLS)    // 4194304

// GEMM tiling: block 128x128, 8 warps of 64x32, fp16 MMA m16n8k16, f16 smem
#define BM 128
#define BN 128
#define BK 32
#define ASTRH 40    // f16 words per A row (80B = 16*5, odd*16 -> conflict-free)
#define BSTRH 136   // f16 words per B row (272B = 16*17)
#define A_ST_H (BM * ASTRH)   // 5120 f16
#define B_ST_H (BK * BSTRH)   // 4352 f16

__device__ int g_len[BSZ * 3];   // per batch: L1 (A), L2 (B), L3 (tar)

// ---------------- mask helpers (dtype auto-detect) -------------------------
__device__ __forceinline__ bool mask_is_u8(const void* m) {
    return *(const unsigned int*)m == 0x01010101u;
}
__device__ __forceinline__ bool mask_at(const void* m, int idx, bool u8) {
    if (u8) return ((const unsigned char*)m)[idx] != 0;
    return ((const unsigned int*)m)[idx] != 0u;
}

__global__ void len_kernel(const void* __restrict__ Am,
                           const void* __restrict__ Bm,
                           const void* __restrict__ Tm) {
    int b = blockIdx.x;
    int tid = threadIdx.x;
    __shared__ int cnt[3];
    if (tid < 3) cnt[tid] = 0;
    __syncthreads();
    const void* base[3] = {Am, Bm, Tm};
    #pragma unroll
    for (int m = 0; m < 3; m++) {
        bool u8 = mask_is_u8(base[m]);
        int v = mask_at(base[m], b * ABATCH + tid, u8) ? 1 : 0;
        #pragma unroll
        for (int o = 16; o > 0; o >>= 1) v += __shfl_down_sync(0xffffffffu, v, o);
        if ((tid & 31) == 0) atomicAdd(&cnt[m], v);
    }
    __syncthreads();
    if (tid < 3) g_len[b * 3 + tid] = cnt[tid];
}

// ---------------------------------------------------------------------------
__device__ __forceinline__ uint32_t smem_u32(const void* p) {
    uint32_t a;
    asm("{ .reg .u64 t; cvta.to.shared.u64 t, %1; cvt.u32.u64 %0, t; }" : "=r"(a) : "l"(p));
    return a;
}
__device__ __forceinline__ uint32_t pack_h2(float lo, float hi) {
    uint32_t d;
    asm("cvt.rn.f16x2.f32 %0, %1, %2;" : "=r"(d) : "f"(hi), "f"(lo));
    return d;
}
__device__ __forceinline__ void mma_f16(float* c, uint32_t a0, uint32_t a1,
                                        uint32_t a2, uint32_t a3,
                                        uint32_t b0, uint32_t b1) {
    asm volatile(
        "mma.sync.aligned.m16n8k16.row.col.f32.f16.f16.f32 "
        "{%0,%1,%2,%3}, {%4,%5,%6,%7}, {%8,%9}, {%0,%1,%2,%3};"
        : "+f"(c[0]), "+f"(c[1]), "+f"(c[2]), "+f"(c[3])
        : "r"(a0), "r"(a1), "r"(a2), "r"(a3), "r"(b0), "r"(b1));
}
__device__ __forceinline__ void ldmatrix_x4(uint32_t* r, uint32_t addr) {
    asm volatile("ldmatrix.sync.aligned.m8n8.x4.shared.b16 {%0,%1,%2,%3}, [%4];"
                 : "=r"(r[0]), "=r"(r[1]), "=r"(r[2]), "=r"(r[3]) : "r"(addr));
}
__device__ __forceinline__ void ldmatrix_x4_t(uint32_t* r, uint32_t addr) {
    asm volatile("ldmatrix.sync.aligned.m8n8.x4.trans.shared.b16 {%0,%1,%2,%3}, [%4];"
                 : "=r"(r[0]), "=r"(r[1]), "=r"(r[2]), "=r"(r[3]) : "r"(addr));
}
__device__ __forceinline__ void sts128(uint32_t addr, uint32_t x, uint32_t y,
                                       uint32_t z, uint32_t w) {
    asm volatile("st.shared.v4.b32 [%0], {%1,%2,%3,%4};"
                 :: "r"(addr), "r"(x), "r"(y), "r"(z), "r"(w) : "memory");
}

__global__ __launch_bounds__(256, 2)
void gemm_kernel(const float* __restrict__ A,
                 const float* __restrict__ Bt,
                 const void* __restrict__ tar,
                 float* __restrict__ C) {
    // f16 tiles stored as uint32 words (2 halves per word)
    __shared__ uint32_t As[2][A_ST_H / 2];
    __shared__ uint32_t Bs[2][B_ST_H / 2];

    const int b  = blockIdx.z;
    const int m0 = blockIdx.x * BN;
    const int i0 = blockIdx.y * BM;
    const int tid = threadIdx.x;
    const int lane = tid & 31;
    const int w = tid >> 5;
    const int wm = w >> 2;      // 0..1 -> 64 rows
    const int wn = w & 3;       // 0..3 -> 32 cols
    const int g = lane >> 2;    // 0..7
    const int r = lane & 3;     // 0..3

    const int L1 = g_len[b * 3 + 0];
    const int L2 = g_len[b * 3 + 1];
    const int Kmin = min(L1, L2);
    const int T = (Kmin + BK - 1) / BK;   // 4..8

    const float* Ab = A + b * ABATCH + i0 * NDIM;
    const float* Bb = Bt + (size_t)b * BBATCH;

    float acc[4][4][4];
    #pragma unroll
    for (int mf = 0; mf < 4; mf++)
        #pragma unroll
        for (int nf = 0; nf < 4; nf++)
            #pragma unroll
            for (int q = 0; q < 4; q++) acc[mf][nf][q] = 0.0f;

    // producer coords
    const int a_row = tid & 127;
    const int a_kg0 = tid >> 7;            // handles kg0, kg0+2
    const int b_k   = tid >> 3;            // 0..31
    const int b_ng0 = tid & 7;             // handles ng0, ng0+8

    const uint32_t as_base[2] = {smem_u32(&As[0][0]), smem_u32(&As[1][0])};
    const uint32_t bs_base[2] = {smem_u32(&Bs[0][0]), smem_u32(&Bs[1][0])};

    float fa[2][8];
    float fb[2][8];

    auto ldg = [&](int t) {
        const int k0 = t * BK;
        #pragma unroll
        for (int h = 0; h < 2; h++) {
            const int kg = a_kg0 + 2 * h;
            const float* ga = Ab + a_row * NDIM + k0 + kg * 8;
            float4 v0 = *reinterpret_cast<const float4*>(ga);
            float4 v1 = *reinterpret_cast<const float4*>(ga + 4);
            fa[h][0] = v0.x; fa[h][1] = v0.y; fa[h][2] = v0.z; fa[h][3] = v0.w;
            fa[h][4] = v1.x; fa[h][5] = v1.y; fa[h][6] = v1.z; fa[h][7] = v1.w;
        }
        const int j = k0 + b_k;
        #pragma unroll
        for (int h = 0; h < 2; h++) {
            const int ng = b_ng0 + 8 * h;
            const float* gb = Bb + (size_t)j * MCOLS + m0 + ng * 8;
            float4 v0 = *reinterpret_cast<const float4*>(gb);
            float4 v1 = *reinterpret_cast<const float4*>(gb + 4);
            fb[h][0] = v0.x; fb[h][1] = v0.y; fb[h][2] = v0.z; fb[h][3] = v0.w;
            fb[h][4] = v1.x; fb[h][5] = v1.y; fb[h][6] = v1.z; fb[h][7] = v1.w;
        }
    };

    auto sts = [&](int t, int s) {
        const int k0 = t * BK;
        #pragma unroll
        for (int h = 0; h < 2; h++) {
            const int kg = a_kg0 + 2 * h;
            const int rem = Kmin - (k0 + kg * 8);
            float e[8];
            #pragma unroll
            for (int q = 0; q < 8; q++) e[q] = (q < rem) ? fa[h][q] : 0.0f;
            sts128(as_base[s] + (a_row * ASTRH + kg * 8) * 2,
                   pack_h2(e[0], e[1]), pack_h2(e[2], e[3]),
                   pack_h2(e[4], e[5]), pack_h2(e[6], e[7]));
        }
        const int j = k0 + b_k;
        const bool okb = (j < Kmin);
        #pragma unroll
        for (int h = 0; h < 2; h++) {
            const int ng = b_ng0 + 8 * h;
            float e[8];
            #pragma unroll
            for (int q = 0; q < 8; q++) e[q] = okb ? fb[h][q] : 0.0f;
            sts128(bs_base[s] + (b_k * BSTRH + ng * 8) * 2,
                   pack_h2(e[0], e[1]), pack_h2(e[2], e[3]),
                   pack_h2(e[4], e[5]), pack_h2(e[6], e[7]));
        }
    };

    // consumer lane addressing
    const int lm = lane & 15;
    const int lh = lane >> 4;   // 0/1
    const uint32_t a_off0 = ((wm * 64 + lm) * ASTRH + lh * 8) * 2;
    const uint32_t b_off0 = (lm * BSTRH + wn * 32 + lh * 8) * 2;

    ldg(0);

    for (int t = 0; t < T; t++) {
        const int s = t & 1;
        sts(t, s);
        __syncthreads();
        if (t + 1 < T) ldg(t + 1);

        #pragma unroll
        for (int ks = 0; ks < 2; ks++) {
            uint32_t af[4][4];
            uint32_t bf[2][4];
            #pragma unroll
            for (int mf = 0; mf < 4; mf++)
                ldmatrix_x4(af[mf], as_base[s] + a_off0
                            + (mf * 16 * ASTRH + ks * 16) * 2);
            #pragma unroll
            for (int pair = 0; pair < 2; pair++)
                ldmatrix_x4_t(bf[pair], bs_base[s] + b_off0
                              + (ks * 16 * BSTRH + pair * 16) * 2);
            #pragma unroll
            for (int mf = 0; mf < 4; mf++) {
                #pragma unroll
                for (int pair = 0; pair < 2; pair++) {
                    mma_f16(acc[mf][pair * 2],     af[mf][0], af[mf][1],
                            af[mf][2], af[mf][3], bf[pair][0], bf[pair][1]);
                    mma_f16(acc[mf][pair * 2 + 1], af[mf][0], af[mf][1],
                            af[mf][2], af[mf][3], bf[pair][2], bf[pair][3]);
                }
            }
        }
        // next iteration's sts(s^1) is ordered after this compute by the
        // __syncthreads at the top of that iteration.
    }

    // ---- epilogue: warp covers 64 rows x 32 cols -> single kcol ----
    const bool u8 = mask_is_u8(tar);
    const int kcol = (m0 >> 6) + (wn >> 1);
    const bool vcol = (kcol < L2);

    bool rmask[4][2];
    #pragma unroll
    for (int mf = 0; mf < 4; mf++) {
        #pragma unroll
        for (int h = 0; h < 2; h++) {
            int i = i0 + wm * 64 + mf * 16 + g + h * 8;
            rmask[mf][h] = vcol && (i < L1)
                           && mask_at(tar, b * ABATCH + i * NDIM + kcol, u8);
        }
    }

    float* Cb = C + (size_t)b * BBATCH;
    #pragma unroll
    for (int mf = 0; mf < 4; mf++) {
        int row = i0 + wm * 64 + mf * 16 + g;
        #pragma unroll
        for (int nf = 0; nf < 4; nf++) {
            int col = m0 + wn * 32 + nf * 8 + r * 2;
            float2 v0 = rmask[mf][0] ? make_float2(acc[mf][nf][0], acc[mf][nf][1])
                                     : make_float2(0.0f, 0.0f);
            float2 v1 = rmask[mf][1] ? make_float2(acc[mf][nf][2], acc[mf][nf][3])
                                     : make_float2(0.0f, 0.0f);
            *reinterpret_cast<float2*>(Cb + (size_t)row * MCOLS + col) = v0;
            *reinterpret_cast<float2*>(Cb + (size_t)(row + 8) * MCOLS + col) = v1;
        }
    }
}

// ---------------------------------------------------------------------------
extern "C" void kernel_launch(void* const* d_in, const int* in_sizes, int n_in,
                              void* d_out, int out_size) {
    (void)in_sizes; (void)n_in; (void)out_size;
    const float* A  = (const float*)d_in[0];
    const void*  Am = d_in[1];
    const float* Bt = (const float*)d_in[2];
    const void*  Bm = d_in[3];
    const void*  Tm = d_in[4];
    float* C = (float*)d_out;

    len_kernel<<<BSZ, 256>>>(Am, Bm, Tm);

    dim3 grid(MCOLS / BN, NDIM / BM, BSZ);
    gemm_kernel<<<grid, 256>>>(A, Bt, Tm, C);
}

// round 10
// speedup vs baseline: 1.2263x; 1.2263x over previous
#include <cuda_runtime.h>
#include <cstdint>

// Problem constants
#define BSZ   16
#define NDIM  256
#define DDIM  64
#define MCOLS (NDIM * DDIM)      // 16384
#define ABATCH (NDIM * NDIM)     // 65536
#define BBATCH (NDIM * MCOLS)    // 4194304

// GEMM tiling: block 128x128, 8 warps of 64x32, fp16 MMA m16n8k16, f16 smem
#define BM 128
#define BN 128
#define BK 32
#define STAGES 3
#define ASTRH 40    // f16 per A row (80B = odd*16 -> ldmatrix conflict-free)
#define BSTRH 136   // f16 per B row (272B = odd*16)
#define A_ST_B (BM * ASTRH * 2)   // 10240 B
#define B_ST_B (BK * BSTRH * 2)   // 8704 B
#define SMEM_BYTES (STAGES * (A_ST_B + B_ST_B))   // 56832 B

// f16 scratch (static device globals; no allocation)
__device__ uint16_t g_Ah[BSZ * ABATCH];    // 2 MB
__device__ uint16_t g_Bh[BSZ * BBATCH];    // 128 MB
__device__ int g_len[BSZ * 3];

// ---------------- mask helpers (dtype auto-detect) -------------------------
__device__ __forceinline__ bool mask_is_u8(const void* m) {
    return *(const unsigned int*)m == 0x01010101u;
}
__device__ __forceinline__ bool mask_at(const void* m, int idx, bool u8) {
    if (u8) return ((const unsigned char*)m)[idx] != 0;
    return ((const unsigned int*)m)[idx] != 0u;
}

__global__ void len_kernel(const void* __restrict__ Am,
                           const void* __restrict__ Bm,
                           const void* __restrict__ Tm) {
    int b = blockIdx.x;
    int tid = threadIdx.x;
    __shared__ int cnt[3];
    if (tid < 3) cnt[tid] = 0;
    __syncthreads();
    const void* base[3] = {Am, Bm, Tm};
    #pragma unroll
    for (int m = 0; m < 3; m++) {
        bool u8 = mask_is_u8(base[m]);
        int v = mask_at(base[m], b * ABATCH + tid, u8) ? 1 : 0;
        #pragma unroll
        for (int o = 16; o > 0; o >>= 1) v += __shfl_down_sync(0xffffffffu, v, o);
        if ((tid & 31) == 0) atomicAdd(&cnt[m], v);
    }
    __syncthreads();
    if (tid < 3) g_len[b * 3 + tid] = cnt[tid];
}

// ---------------------------------------------------------------------------
__device__ __forceinline__ uint32_t pack_h2(float lo, float hi) {
    uint32_t d;
    asm("cvt.rn.f16x2.f32 %0, %1, %2;" : "=r"(d) : "f"(hi), "f"(lo));
    return d;
}

// f32 -> f16 conversion pass. Blocks [0, NB_B): B rows j < Kmin only.
// Blocks [NB_B, NB_B+NB_A): all of A.
#define NB_B ((BSZ * BBATCH / 8) / 256)     // 32768
#define NB_A ((BSZ * ABATCH / 8) / 256)     // 512
__global__ void conv_kernel(const float* __restrict__ A,
                            const float* __restrict__ Bt) {
    if (blockIdx.x < NB_B) {
        int c = blockIdx.x * 256 + threadIdx.x;       // 8-elem chunk id
        int b = c / (BBATCH / 8);
        int rem = c - b * (BBATCH / 8);
        int j = rem / (MCOLS / 8);
        int Kmin = min(g_len[b * 3], g_len[b * 3 + 1]);
        if (j >= Kmin) return;
        const float4* src = reinterpret_cast<const float4*>(Bt) + c * 2;
        float4 v0 = src[0], v1 = src[1];
        uint4 o = make_uint4(pack_h2(v0.x, v0.y), pack_h2(v0.z, v0.w),
                             pack_h2(v1.x, v1.y), pack_h2(v1.z, v1.w));
        *(reinterpret_cast<uint4*>(g_Bh) + c) = o;
    } else {
        int c = (blockIdx.x - NB_B) * 256 + threadIdx.x;
        const float4* src = reinterpret_cast<const float4*>(A) + c * 2;
        float4 v0 = src[0], v1 = src[1];
        uint4 o = make_uint4(pack_h2(v0.x, v0.y), pack_h2(v0.z, v0.w),
                             pack_h2(v1.x, v1.y), pack_h2(v1.z, v1.w));
        *(reinterpret_cast<uint4*>(g_Ah) + c) = o;
    }
}

// ---------------------------------------------------------------------------
__device__ __forceinline__ void cp_async16(uint32_t smem_addr, const void* gmem,
                                           int src_bytes) {
    asm volatile("cp.async.cg.shared.global [%0], [%1], 16, %2;\n"
                 :: "r"(smem_addr), "l"(gmem), "r"(src_bytes));
}
__device__ __forceinline__ uint32_t smem_u32(const void* p) {
    uint32_t a;
    asm("{ .reg .u64 t; cvta.to.shared.u64 t, %1; cvt.u32.u64 %0, t; }" : "=r"(a) : "l"(p));
    return a;
}
__device__ __forceinline__ void mma_f16(float* c, uint32_t a0, uint32_t a1,
                                        uint32_t a2, uint32_t a3,
                                        uint32_t b0, uint32_t b1) {
    asm volatile(
        "mma.sync.aligned.m16n8k16.row.col.f32.f16.f16.f32 "
        "{%0,%1,%2,%3}, {%4,%5,%6,%7}, {%8,%9}, {%0,%1,%2,%3};"
        : "+f"(c[0]), "+f"(c[1]), "+f"(c[2]), "+f"(c[3])
        : "r"(a0), "r"(a1), "r"(a2), "r"(a3), "r"(b0), "r"(b1));
}
__device__ __forceinline__ void ldmatrix_x4(uint32_t* r, uint32_t addr) {
    asm volatile("ldmatrix.sync.aligned.m8n8.x4.shared.b16 {%0,%1,%2,%3}, [%4];"
                 : "=r"(r[0]), "=r"(r[1]), "=r"(r[2]), "=r"(r[3]) : "r"(addr));
}
__device__ __forceinline__ void ldmatrix_x4_t(uint32_t* r, uint32_t addr) {
    asm volatile("ldmatrix.sync.aligned.m8n8.x4.trans.shared.b16 {%0,%1,%2,%3}, [%4];"
                 : "=r"(r[0]), "=r"(r[1]), "=r"(r[2]), "=r"(r[3]) : "r"(addr));
}

__global__ __launch_bounds__(256, 2)
void gemm_kernel(const void* __restrict__ tar, float* __restrict__ C) {
    extern __shared__ char smem[];
    uint32_t as_base[STAGES], bs_base[STAGES];
    #pragma unroll
    for (int s = 0; s < STAGES; s++) {
        as_base[s] = smem_u32(smem + s * A_ST_B);
        bs_base[s] = smem_u32(smem + STAGES * A_ST_B + s * B_ST_B);
    }

    const int b  = blockIdx.z;
    const int m0 = blockIdx.x * BN;
    const int i0 = blockIdx.y * BM;
    const int tid = threadIdx.x;
    const int lane = tid & 31;
    const int w = tid >> 5;
    const int wm = w >> 2;      // 0..1 -> 64 rows
    const int wn = w & 3;       // 0..3 -> 32 cols
    const int g = lane >> 2;    // 0..7
    const int r = lane & 3;     // 0..3

    const int L1 = g_len[b * 3 + 0];
    const int L2 = g_len[b * 3 + 1];
    const int Kmin = min(L1, L2);
    const int T = (Kmin + BK - 1) / BK;   // 4..8

    const uint16_t* Ab = g_Ah + b * ABATCH + i0 * NDIM;
    const uint16_t* Bb = g_Bh + (size_t)b * BBATCH + m0;

    float acc[4][4][4];
    #pragma unroll
    for (int mf = 0; mf < 4; mf++)
        #pragma unroll
        for (int nf = 0; nf < 4; nf++)
            #pragma unroll
            for (int q = 0; q < 4; q++) acc[mf][nf][q] = 0.0f;

    // producer coords: A 512 chunks (128 rows x 4), B 512 chunks (32 rows x 16)
    const int a_r0 = tid >> 2;       // rows tid>>2, +64
    const int a_c  = tid & 3;        // 8-f16 chunk in row
    const int b_k0 = tid >> 4;       // rows tid>>4, +16
    const int b_c  = tid & 15;

    auto issue = [&](int t, int s) {
        const int k0 = t * BK;
        #pragma unroll
        for (int q = 0; q < 2; q++) {
            int row = a_r0 + q * 64;
            int kk = k0 + a_c * 8;
            int nb = 2 * (Kmin - kk);
            nb = nb < 0 ? 0 : (nb > 16 ? 16 : nb);
            cp_async16(as_base[s] + (row * ASTRH + a_c * 8) * 2,
                       Ab + row * NDIM + kk, nb);
        }
        #pragma unroll
        for (int q = 0; q < 2; q++) {
            int k = b_k0 + q * 16;
            int j = k0 + k;
            cp_async16(bs_base[s] + (k * BSTRH + b_c * 8) * 2,
                       Bb + (size_t)j * MCOLS + b_c * 8,
                       (j < Kmin) ? 16 : 0);
        }
        asm volatile("cp.async.commit_group;\n" ::: "memory");
    };

    // consumer lane addressing (verified in R8)
    const int lm = lane & 15;
    const int lh = lane >> 4;
    const uint32_t a_off0 = ((wm * 64 + lm) * ASTRH + lh * 8) * 2;
    const uint32_t b_off0 = (lm * BSTRH + wn * 32 + lh * 8) * 2;

    issue(0, 0);
    issue(1, 1);

    for (int t = 0; t < T; t++) {
        const int s = t % STAGES;
        if (t + 1 < T) {
            asm volatile("cp.async.wait_group 1;\n" ::: "memory");
        } else {
            asm volatile("cp.async.wait_group 0;\n" ::: "memory");
        }
        __syncthreads();

        #pragma unroll
        for (int ks = 0; ks < 2; ks++) {
            uint32_t af[4][4];
            uint32_t bf[2][4];
            #pragma unroll
            for (int mf = 0; mf < 4; mf++)
                ldmatrix_x4(af[mf], as_base[s] + a_off0
                            + (mf * 16 * ASTRH + ks * 16) * 2);
            #pragma unroll
            for (int pair = 0; pair < 2; pair++)
                ldmatrix_x4_t(bf[pair], bs_base[s] + b_off0
                              + (ks * 16 * BSTRH + pair * 16) * 2);
            #pragma unroll
            for (int mf = 0; mf < 4; mf++) {
                #pragma unroll
                for (int pair = 0; pair < 2; pair++) {
                    mma_f16(acc[mf][pair * 2],     af[mf][0], af[mf][1],
                            af[mf][2], af[mf][3], bf[pair][0], bf[pair][1]);
                    mma_f16(acc[mf][pair * 2 + 1], af[mf][0], af[mf][1],
                            af[mf][2], af[mf][3], bf[pair][2], bf[pair][3]);
                }
            }
        }

        if (t + 2 < T) issue(t + 2, (t + 2) % STAGES);  // stage consumed at t-1
    }

    // ---- epilogue: warp covers 64 rows x 32 cols -> single kcol ----
    const bool u8 = mask_is_u8(tar);
    const int kcol = (m0 >> 6) + (wn >> 1);
    const bool vcol = (kcol < L2);

    bool rmask[4][2];
    #pragma unroll
    for (int mf = 0; mf < 4; mf++) {
        #pragma unroll
        for (int h = 0; h < 2; h++) {
            int i = i0 + wm * 64 + mf * 16 + g + h * 8;
            rmask[mf][h] = vcol && (i < L1)
                           && mask_at(tar, b * ABATCH + i * NDIM + kcol, u8);
        }
    }

    float* Cb = C + (size_t)b * BBATCH;
    #pragma unroll
    for (int mf = 0; mf < 4; mf++) {
        int row = i0 + wm * 64 + mf * 16 + g;
        #pragma unroll
        for (int nf = 0; nf < 4; nf++) {
            int col = m0 + wn * 32 + nf * 8 + r * 2;
            float2 v0 = rmask[mf][0] ? make_float2(acc[mf][nf][0], acc[mf][nf][1])
                                     : make_float2(0.0f, 0.0f);
            float2 v1 = rmask[mf][1] ? make_float2(acc[mf][nf][2], acc[mf][nf][3])
                                     : make_float2(0.0f, 0.0f);
            *reinterpret_cast<float2*>(Cb + (size_t)row * MCOLS + col) = v0;
            *reinterpret_cast<float2*>(Cb + (size_t)(row + 8) * MCOLS + col) = v1;
        }
    }
}

// ---------------------------------------------------------------------------
extern "C" void kernel_launch(void* const* d_in, const int* in_sizes, int n_in,
                              void* d_out, int out_size) {
    (void)in_sizes; (void)n_in; (void)out_size;
    const float* A  = (const float*)d_in[0];
    const void*  Am = d_in[1];
    const float* Bt = (const float*)d_in[2];
    const void*  Bm = d_in[3];
    const void*  Tm = d_in[4];
    float* C = (float*)d_out;

    cudaFuncSetAttribute(gemm_kernel,
                         cudaFuncAttributeMaxDynamicSharedMemorySize, SMEM_BYTES);

    len_kernel<<<BSZ, 256>>>(Am, Bm, Tm);
    conv_kernel<<<NB_B + NB_A, 256>>>(A, Bt);

    dim3 grid(MCOLS / BN, NDIM / BM, BSZ);
    gemm_kernel<<<grid, 256, SMEM_BYTES>>>(Tm, C);
}

// round 11
// speedup vs baseline: 1.2460x; 1.0161x over previous
#include <cuda_runtime.h>
#include <cstdint>

// Problem constants
#define BSZ   16
#define NDIM  256
#define DDIM  64
#define MCOLS (NDIM * DDIM)      // 16384
#define ABATCH (NDIM * NDIM)     // 65536
#define BBATCH (NDIM * MCOLS)    // 4194304

// GEMM tiling: block 128x128, 8 warps of 64x32, fp16 MMA m16n8k16, f16 smem
#define BM 128
#define BN 128
#define BK 64
#define KSTEPS 4
#define STAGES 3
#define ASTRH 72    // f16 per A row (144B = 9*16, odd -> ldmatrix conflict-free)
#define BSTRH 136   // f16 per B row (272B = 17*16, odd)
#define A_ST_B (BM * ASTRH * 2)   // 18432 B
#define B_ST_B (BK * BSTRH * 2)   // 17408 B
#define SMEM_BYTES (STAGES * (A_ST_B + B_ST_B))   // 107520 B

// f16 scratch (static device globals; no allocation)
__device__ uint16_t g_Ah[BSZ * ABATCH];    // 2 MB
__device__ uint16_t g_Bh[BSZ * BBATCH];    // 128 MB
__device__ int g_len[BSZ * 3];

// ---------------- mask helpers (dtype auto-detect) -------------------------
__device__ __forceinline__ bool mask_is_u8(const void* m) {
    return *(const unsigned int*)m == 0x01010101u;
}
__device__ __forceinline__ bool mask_at(const void* m, int idx, bool u8) {
    if (u8) return ((const unsigned char*)m)[idx] != 0;
    return ((const unsigned int*)m)[idx] != 0u;
}

__global__ void len_kernel(const void* __restrict__ Am,
                           const void* __restrict__ Bm,
                           const void* __restrict__ Tm) {
    int b = blockIdx.x;
    int tid = threadIdx.x;
    __shared__ int cnt[3];
    if (tid < 3) cnt[tid] = 0;
    __syncthreads();
    const void* base[3] = {Am, Bm, Tm};
    #pragma unroll
    for (int m = 0; m < 3; m++) {
        bool u8 = mask_is_u8(base[m]);
        int v = mask_at(base[m], b * ABATCH + tid, u8) ? 1 : 0;
        #pragma unroll
        for (int o = 16; o > 0; o >>= 1) v += __shfl_down_sync(0xffffffffu, v, o);
        if ((tid & 31) == 0) atomicAdd(&cnt[m], v);
    }
    __syncthreads();
    if (tid < 3) g_len[b * 3 + tid] = cnt[tid];
}

// ---------------------------------------------------------------------------
__device__ __forceinline__ uint32_t pack_h2(float lo, float hi) {
    uint32_t d;
    asm("cvt.rn.f16x2.f32 %0, %1, %2;" : "=r"(d) : "f"(hi), "f"(lo));
    return d;
}

// f32 -> f16 conversion pass. Blocks [0, NB_B): B rows j < Kmin only.
// Blocks [NB_B, NB_B+NB_A): all of A.
#define NB_B ((BSZ * BBATCH / 8) / 256)     // 32768
#define NB_A ((BSZ * ABATCH / 8) / 256)     // 512
__global__ void conv_kernel(const float* __restrict__ A,
                            const float* __restrict__ Bt) {
    if (blockIdx.x < NB_B) {
        int c = blockIdx.x * 256 + threadIdx.x;       // 8-elem chunk id
        int b = c / (BBATCH / 8);
        int rem = c - b * (BBATCH / 8);
        int j = rem / (MCOLS / 8);
        int Kmin = min(g_len[b * 3], g_len[b * 3 + 1]);
        if (j >= Kmin) return;
        const float4* src = reinterpret_cast<const float4*>(Bt) + c * 2;
        float4 v0 = src[0], v1 = src[1];
        uint4 o = make_uint4(pack_h2(v0.x, v0.y), pack_h2(v0.z, v0.w),
                             pack_h2(v1.x, v1.y), pack_h2(v1.z, v1.w));
        *(reinterpret_cast<uint4*>(g_Bh) + c) = o;
    } else {
        int c = (blockIdx.x - NB_B) * 256 + threadIdx.x;
        const float4* src = reinterpret_cast<const float4*>(A) + c * 2;
        float4 v0 = src[0], v1 = src[1];
        uint4 o = make_uint4(pack_h2(v0.x, v0.y), pack_h2(v0.z, v0.w),
                             pack_h2(v1.x, v1.y), pack_h2(v1.z, v1.w));
        *(reinterpret_cast<uint4*>(g_Ah) + c) = o;
    }
}

// ---------------------------------------------------------------------------
__device__ __forceinline__ void cp_async16(uint32_t smem_addr, const void* gmem,
                                           int src_bytes) {
    asm volatile("cp.async.cg.shared.global [%0], [%1], 16, %2;\n"
                 :: "r"(smem_addr), "l"(gmem), "r"(src_bytes));
}
__device__ __forceinline__ uint32_t smem_u32(const void* p) {
    uint32_t a;
    asm("{ .reg .u64 t; cvta.to.shared.u64 t, %1; cvt.u32.u64 %0, t; }" : "=r"(a) : "l"(p));
    return a;
}
__device__ __forceinline__ void mma_f16(float* c, uint32_t a0, uint32_t a1,
                                        uint32_t a2, uint32_t a3,
                                        uint32_t b0, uint32_t b1) {
    asm volatile(
        "mma.sync.aligned.m16n8k16.row.col.f32.f16.f16.f32 "
        "{%0,%1,%2,%3}, {%4,%5,%6,%7}, {%8,%9}, {%0,%1,%2,%3};"
        : "+f"(c[0]), "+f"(c[1]), "+f"(c[2]), "+f"(c[3])
        : "r"(a0), "r"(a1), "r"(a2), "r"(a3), "r"(b0), "r"(b1));
}
__device__ __forceinline__ void ldmatrix_x4(uint32_t* r, uint32_t addr) {
    asm volatile("ldmatrix.sync.aligned.m8n8.x4.shared.b16 {%0,%1,%2,%3}, [%4];"
                 : "=r"(r[0]), "=r"(r[1]), "=r"(r[2]), "=r"(r[3]) : "r"(addr));
}
__device__ __forceinline__ void ldmatrix_x4_t(uint32_t* r, uint32_t addr) {
    asm volatile("ldmatrix.sync.aligned.m8n8.x4.trans.shared.b16 {%0,%1,%2,%3}, [%4];"
                 : "=r"(r[0]), "=r"(r[1]), "=r"(r[2]), "=r"(r[3]) : "r"(addr));
}

__global__ __launch_bounds__(256, 2)
void gemm_kernel(const void* __restrict__ tar, float* __restrict__ C) {
    extern __shared__ char smem[];
    uint32_t as_base[STAGES], bs_base[STAGES];
    #pragma unroll
    for (int s = 0; s < STAGES; s++) {
        as_base[s] = smem_u32(smem + s * A_ST_B);
        bs_base[s] = smem_u32(smem + STAGES * A_ST_B + s * B_ST_B);
    }

    const int b  = blockIdx.z;
    const int m0 = blockIdx.x * BN;
    const int i0 = blockIdx.y * BM;
    const int tid = threadIdx.x;
    const int lane = tid & 31;
    const int w = tid >> 5;
    const int wm = w >> 2;      // 0..1 -> 64 rows
    const int wn = w & 3;       // 0..3 -> 32 cols
    const int g = lane >> 2;    // 0..7
    const int r = lane & 3;     // 0..3

    const int L1 = g_len[b * 3 + 0];
    const int L2 = g_len[b * 3 + 1];
    const int Kmin = min(L1, L2);
    const int T = (Kmin + BK - 1) / BK;   // 2..4

    const uint16_t* Ab = g_Ah + b * ABATCH + i0 * NDIM;
    const uint16_t* Bb = g_Bh + (size_t)b * BBATCH + m0;

    float acc[4][4][4];
    #pragma unroll
    for (int mf = 0; mf < 4; mf++)
        #pragma unroll
        for (int nf = 0; nf < 4; nf++)
            #pragma unroll
            for (int q = 0; q < 4; q++) acc[mf][nf][q] = 0.0f;

    // producer coords: A 1024 chunks (128 rows x 8), B 1024 chunks (64 rows x 16)
    const int a_r0 = tid >> 3;       // rows tid>>3, +32q
    const int a_c  = tid & 7;        // 8-f16 chunk in row (64 f16 per row)
    const int b_k0 = tid >> 4;       // rows tid>>4, +16q
    const int b_c  = tid & 15;

    auto issue = [&](int t, int s) {
        const int k0 = t * BK;
        #pragma unroll
        for (int q = 0; q < 4; q++) {
            int row = a_r0 + q * 32;
            int kk = k0 + a_c * 8;
            int nb = 2 * (Kmin - kk);
            nb = nb < 0 ? 0 : (nb > 16 ? 16 : nb);
            cp_async16(as_base[s] + (row * ASTRH + a_c * 8) * 2,
                       Ab + row * NDIM + kk, nb);
        }
        #pragma unroll
        for (int q = 0; q < 4; q++) {
            int k = b_k0 + q * 16;
            int j = k0 + k;
            cp_async16(bs_base[s] + (k * BSTRH + b_c * 8) * 2,
                       Bb + (size_t)j * MCOLS + b_c * 8,
                       (j < Kmin) ? 16 : 0);
        }
        asm volatile("cp.async.commit_group;\n" ::: "memory");
    };

    // consumer lane addressing (layout verified in R8/R10)
    const int lm = lane & 15;
    const int lh = lane >> 4;
    const uint32_t a_off0 = ((wm * 64 + lm) * ASTRH + lh * 8) * 2;
    const uint32_t b_off0 = (lm * BSTRH + wn * 32 + lh * 8) * 2;

    issue(0, 0);
    issue(1, 1);

    for (int t = 0; t < T; t++) {
        const int s = t % STAGES;
        if (t + 1 < T) {
            asm volatile("cp.async.wait_group 1;\n" ::: "memory");
        } else {
            asm volatile("cp.async.wait_group 0;\n" ::: "memory");
        }
        __syncthreads();

        #pragma unroll
        for (int ks = 0; ks < KSTEPS; ks++) {
            uint32_t af[4][4];
            uint32_t bf[2][4];
            #pragma unroll
            for (int mf = 0; mf < 4; mf++)
                ldmatrix_x4(af[mf], as_base[s] + a_off0
                            + (mf * 16 * ASTRH + ks * 16) * 2);
            #pragma unroll
            for (int pair = 0; pair < 2; pair++)
                ldmatrix_x4_t(bf[pair], bs_base[s] + b_off0
                              + (ks * 16 * BSTRH + pair * 16) * 2);
            #pragma unroll
            for (int mf = 0; mf < 4; mf++) {
                #pragma unroll
                for (int pair = 0; pair < 2; pair++) {
                    mma_f16(acc[mf][pair * 2],     af[mf][0], af[mf][1],
                            af[mf][2], af[mf][3], bf[pair][0], bf[pair][1]);
                    mma_f16(acc[mf][pair * 2 + 1], af[mf][0], af[mf][1],
                            af[mf][2], af[mf][3], bf[pair][2], bf[pair][3]);
                }
            }
        }

        if (t + 2 < T) issue(t + 2, (t + 2) % STAGES);  // stage consumed at t-1
    }

    // ---- epilogue: warp covers 64 rows x 32 cols -> single kcol ----
    const bool u8 = mask_is_u8(tar);
    const int kcol = (m0 >> 6) + (wn >> 1);
    const bool vcol = (kcol < L2);

    bool rmask[4][2];
    #pragma unroll
    for (int mf = 0; mf < 4; mf++) {
        #pragma unroll
        for (int h = 0; h < 2; h++) {
            int i = i0 + wm * 64 + mf * 16 + g + h * 8;
            rmask[mf][h] = vcol && (i < L1)
                           && mask_at(tar, b * ABATCH + i * NDIM + kcol, u8);
        }
    }

    float* Cb = C + (size_t)b * BBATCH;
    #pragma unroll
    for (int mf = 0; mf < 4; mf++) {
        int row = i0 + wm * 64 + mf * 16 + g;
        #pragma unroll
        for (int nf = 0; nf < 4; nf++) {
            int col = m0 + wn * 32 + nf * 8 + r * 2;
            float2 v0 = rmask[mf][0] ? make_float2(acc[mf][nf][0], acc[mf][nf][1])
                                     : make_float2(0.0f, 0.0f);
            float2 v1 = rmask[mf][1] ? make_float2(acc[mf][nf][2], acc[mf][nf][3])
                                     : make_float2(0.0f, 0.0f);
            *reinterpret_cast<float2*>(Cb + (size_t)row * MCOLS + col) = v0;
            *reinterpret_cast<float2*>(Cb + (size_t)(row + 8) * MCOLS + col) = v1;
        }
    }
}

// ---------------------------------------------------------------------------
extern "C" void kernel_launch(void* const* d_in, const int* in_sizes, int n_in,
                              void* d_out, int out_size) {
    (void)in_sizes; (void)n_in; (void)out_size;
    const float* A  = (const float*)d_in[0];
    const void*  Am = d_in[1];
    const float* Bt = (const float*)d_in[2];
    const void*  Bm = d_in[3];
    const void*  Tm = d_in[4];
    float* C = (float*)d_out;

    cudaFuncSetAttribute(gemm_kernel,
                         cudaFuncAttributeMaxDynamicSharedMemorySize, SMEM_BYTES);

    len_kernel<<<BSZ, 256>>>(Am, Bm, Tm);
    conv_kernel<<<NB_B + NB_A, 256>>>(A, Bt);

    dim3 grid(MCOLS / BN, NDIM / BM, BSZ);
    gemm_kernel<<<grid, 256, SMEM_BYTES>>>(Tm, C);
}